// round 17
// baseline (speedup 1.0000x reference)
#include <cuda_runtime.h>
#include <cuda_fp16.h>

#define B_  2048
#define T_  40
#define H_  128
#define V_  4450
#define VP_ 4480   // 70 * 64, padded vocab
#define C_  102
#define CP_ 104    // padded classes (13 * 8)
#define CW_ 52     // CP_/2 f16x2 words
#define G3  384    // 3H
#define GW_ 192    // G3/2 f16x2 words
#define BT_ (B_ * T_)

// Scratch: __device__ globals (the sanctioned no-alloc workaround)
// tokG layout is GATHER-NATIVE for the scan: word index = ct*24 + qid*6 + (2g+nf)
__device__ unsigned g_tokG[2][VP_][GW_];   // per-token input gates, f16x2 (b_ih + b_hh[r,z] folded)
__device__ unsigned g_mix [2][B_][T_][64]; // mixed fwd/bwd states, f16x2 words

// ---------------------------------------------------------------- helpers ---
__device__ __forceinline__ unsigned pack_f16(float lo, float hi) {
    unsigned r; asm("cvt.rn.f16x2.f32 %0, %1, %2;" : "=r"(r) : "f"(hi), "f"(lo)); return r;
}
__device__ __forceinline__ __half2 u2h2(unsigned u) { return *reinterpret_cast<__half2*>(&u); }
__device__ __forceinline__ unsigned h22u(__half2 h) { return *reinterpret_cast<unsigned*>(&h); }
__device__ __forceinline__ float2 h2f(unsigned u) { return __half22float2(u2h2(u)); }
__device__ __forceinline__ __half2 tanh2(__half2 x) {
    unsigned u = h22u(x), y;
    asm("tanh.approx.f16x2 %0, %1;" : "=r"(y) : "r"(u));
    return u2h2(y);
}
__device__ __forceinline__ void mma_f16(float* d,
                                        unsigned a0, unsigned a1, unsigned a2, unsigned a3,
                                        unsigned b0, unsigned b1) {
    asm volatile(
        "mma.sync.aligned.m16n8k16.row.col.f32.f16.f16.f32 "
        "{%0,%1,%2,%3},{%4,%5,%6,%7},{%8,%9},{%0,%1,%2,%3};"
        : "+f"(d[0]), "+f"(d[1]), "+f"(d[2]), "+f"(d[3])
        : "r"(a0), "r"(a1), "r"(a2), "r"(a3), "r"(b0), "r"(b1));
}
__device__ __forceinline__ void ldsm_x4(unsigned& r0, unsigned& r1, unsigned& r2, unsigned& r3,
                                        unsigned a) {
    asm volatile("ldmatrix.sync.aligned.m8n8.x4.shared.b16 {%0,%1,%2,%3}, [%4];"
                 : "=r"(r0), "=r"(r1), "=r"(r2), "=r"(r3) : "r"(a));
}
__device__ __forceinline__ void ldsm_x2t(unsigned& r0, unsigned& r1, unsigned a) {
    asm volatile("ldmatrix.sync.aligned.m8n8.x2.trans.shared.b16 {%0,%1}, [%2];"
                 : "=r"(r0), "=r"(r1) : "r"(a));
}

// --------------------------------------------------------------- kernel 1 ---
// Token-gate table via f16 MMA, f16x2 output in the gather-native layout.
__global__ __launch_bounds__(256, 2) void tok_gx_kernel(const float* __restrict__ emb_a,
                                                        const float* __restrict__ emb_c,
                                                        const float* __restrict__ W_ih,
                                                        const float* __restrict__ b_ih,
                                                        const float* __restrict__ b_hh) {
    extern __shared__ unsigned smu[];
    unsigned* Wb  = smu;                     // [192][64] f16x2 words, swizzled
    unsigned* Ab  = smu + 192 * 64;          // [64][64] f16x2 words, swizzled
    float*    bias = (float*)(Ab + 64 * 64); // [192]

    const int tid = threadIdx.x;
    const int tile = blockIdx.x, stream = blockIdx.y, half = blockIdx.z;
    const float* emb = (stream == 0) ? emb_a : emb_c;
    const int row0 = tile * 64;
    const int nbase = half * 192;

    for (int i = tid; i < 192 * 64; i += 256) {
        int n = i >> 6, w = i & 63;
        float2 v = *(const float2*)(W_ih + (size_t)(nbase + n) * 128 + 2 * w);
        Wb[(n << 6) + (w ^ ((n & 7) << 2))] = pack_f16(v.x, v.y);
    }
    for (int i = tid; i < 192; i += 256) {
        int n = nbase + i;
        bias[i] = b_ih[n] + (n < 256 ? b_hh[n] : 0.f);
    }
    for (int i = tid; i < 64 * 64; i += 256) {
        int r = i >> 6, w = i & 63;
        int vr = row0 + r; if (vr >= V_) vr = V_ - 1;
        float2 v = *(const float2*)(emb + (size_t)vr * H_ + 2 * w);
        Ab[(r << 6) + (w ^ ((r & 7) << 2))] = pack_f16(v.x, v.y);
    }
    __syncthreads();

    const int warp = tid >> 5, lane = tid & 31;
    const int rt = warp & 3, ct = warp >> 2;
    const int gid = lane >> 2, qid = lane & 3;
    const int gsw = gid << 2;
    const int ra0 = (rt * 16 + gid) << 6;
    const int ra1 = ra0 + (8 << 6);

    float acc[12][4];
#pragma unroll
    for (int nt = 0; nt < 12; nt++)
#pragma unroll
        for (int e = 0; e < 4; e++) acc[nt][e] = 0.f;

#pragma unroll
    for (int kb = 0; kb < 8; kb++) {
        const int k0 = kb * 8;
        unsigned a0 = Ab[ra0 + ((k0 + qid)     ^ gsw)];
        unsigned a1 = Ab[ra1 + ((k0 + qid)     ^ gsw)];
        unsigned a2 = Ab[ra0 + ((k0 + qid + 4) ^ gsw)];
        unsigned a3 = Ab[ra1 + ((k0 + qid + 4) ^ gsw)];
#pragma unroll
        for (int nt = 0; nt < 12; nt++) {
            const unsigned* wr = Wb + ((ct * 96 + nt * 8 + gid) << 6);
            unsigned b0 = wr[(k0 + qid)     ^ gsw];
            unsigned b1 = wr[(k0 + qid + 4) ^ gsw];
            mma_f16(acc[nt], a0, a1, a2, a3, b0, b1);
        }
    }

#pragma unroll
    for (int m = 0; m < 2; m++) {
        const int row = rt * 16 + gid + 8 * m;
        unsigned* gp = &g_tokG[stream][row0 + row][0];
#pragma unroll
        for (int nt = 0; nt < 12; nt++) {
            const int nl = ct * 96 + nt * 8 + qid * 2;  // local col (0..191)
            const int w_old = half * 96 + ct * 48 + nt * 4 + qid;
            const int g = w_old >> 6, rem = w_old & 63;
            const int sct = rem >> 3, snf = (rem >> 2) & 1, sq = rem & 3;
            gp[sct * 24 + sq * 6 + g * 2 + snf] =
                pack_f16(acc[nt][2 * m] + bias[nl], acc[nt][2 * m + 1] + bias[nl + 1]);
        }
    }
}

// --------------------------------------------------------------- kernel 2 ---
// 4 GRU scans, f16 MMA with LDMATRIX fragment loads. Block = (scan, 32-row
// tile), 256 blocks, 2/SM. Gate words fetched as 3 contiguous LDG.64 per row.
__global__ __launch_bounds__(256, 2) void scan_kernel(const float* __restrict__ W_hh,
                                                      const float* __restrict__ b_hh,
                                                      const int* __restrict__ tokens) {
    extern __shared__ unsigned smu[];
    unsigned* Ws   = smu;                       // 384 * 64 f16x2 words, swizzled
    unsigned* Hbuf = smu + 384 * 64;            // 2 x [32*64] words
    unsigned* bnw  = Hbuf + 2 * 32 * 64;        // 64 f16x2 = b_hh for n gate

    const int tid = threadIdx.x;
    const int scan = blockIdx.x >> 6, tile = blockIdx.x & 63;
    const int stream = scan >> 1, rev = scan & 1;
    const int row0 = tile * 32;

    for (int i = tid; i < 384 * 64; i += 256) {
        int n = i >> 6, w = i & 63;
        float2 v = *(const float2*)(W_hh + n * 128 + 2 * w);
        Ws[(n << 6) + (w ^ ((n & 7) << 2))] = pack_f16(v.x, v.y);
    }
    for (int i = tid; i < 32 * 64; i += 256) Hbuf[i] = 0u;   // buffer 0 only
    if (tid < 64) bnw[tid] = pack_f16(b_hh[256 + 2 * tid], b_hh[256 + 2 * tid + 1]);
    __syncthreads();

    const int ct = tid >> 5, lane = tid & 31;   // ct: 16-h-col slice (0..7)
    const int gid = lane >> 2, qid = lane & 3;
    const unsigned* tokG = &g_tokG[stream][0][0];
    const int gidx0 = ct * 24 + qid * 6;        // contiguous 6-word gate base

    const __half2 bn0 = u2h2(bnw[ct * 8 + qid]);
    const __half2 bn1 = u2h2(bnw[ct * 8 + 4 + qid]);

    const unsigned ws_sa = (unsigned)__cvta_generic_to_shared(Ws);
    const unsigned hb_sa = (unsigned)__cvta_generic_to_shared(Hbuf);
    const int l7 = lane & 7, grp = lane >> 3;
    const int swz  = l7 << 2;
    const int wselA = (grp >> 1) << 2;
    const int wselB = grp << 2;
    const unsigned rowA0 = (unsigned)((l7 + ((grp & 1) << 3)) << 8);
    const unsigned rowA1 = rowA0 + (16 << 8);
    unsigned bAddr[3][2];
#pragma unroll
    for (int g = 0; g < 3; g++)
#pragma unroll
        for (int nt = 0; nt < 2; nt++)
            bAddr[g][nt] = ws_sa + (unsigned)((g * 128 + ct * 16 + nt * 8 + l7) << 8);

    const __half2 chalf = __floats2half2_rn(0.5f, 0.5f);
    __half2 hreg[4][2];
#pragma unroll
    for (int e = 0; e < 4; e++)
#pragma unroll
        for (int nt = 0; nt < 2; nt++) hreg[e][nt] = __floats2half2_rn(0.f, 0.f);

    for (int step = 0; step < 40; step++) {
        const int t = rev ? 39 - step : step;
        unsigned* Hnxt = Hbuf + ((step & 1) ? 0 : 32 * 64);
        const unsigned hcur_sa = hb_sa + (unsigned)((step & 1) << 13);

        int tk[4];
#pragma unroll
        for (int e = 0; e < 4; e++)
            tk[e] = __ldg(&tokens[(row0 + gid + 8 * e) * T_ + t]);

        unsigned gw[4][6];
#pragma unroll
        for (int e = 0; e < 4; e++) {
            const uint2* gr = (const uint2*)(tokG + (size_t)tk[e] * GW_ + gidx0);
            uint2 p0 = __ldg(gr), p1 = __ldg(gr + 1), p2 = __ldg(gr + 2);
            gw[e][0] = p0.x; gw[e][1] = p0.y;
            gw[e][2] = p1.x; gw[e][3] = p1.y;
            gw[e][4] = p2.x; gw[e][5] = p2.y;
        }

        float acc[3][2][2][4];
#pragma unroll
        for (int g = 0; g < 3; g++)
#pragma unroll
            for (int nt = 0; nt < 2; nt++)
#pragma unroll
                for (int mt = 0; mt < 2; mt++)
#pragma unroll
                    for (int e = 0; e < 4; e++) acc[g][nt][mt][e] = 0.f;

#pragma unroll
        for (int p = 0; p < 4; p++) {
            const unsigned wA0 = (unsigned)(((p * 16 + wselA)     ^ swz) << 2);
            const unsigned wA1 = (unsigned)(((p * 16 + 8 + wselA) ^ swz) << 2);
            const unsigned wB  = (unsigned)(((p * 16 + wselB)     ^ swz) << 2);
            unsigned ae0[4], ae1[4], ao0[4], ao1[4];
            ldsm_x4(ae0[0], ae0[1], ae0[2], ae0[3], hcur_sa + rowA0 + wA0);
            ldsm_x4(ae1[0], ae1[1], ae1[2], ae1[3], hcur_sa + rowA1 + wA0);
            ldsm_x4(ao0[0], ao0[1], ao0[2], ao0[3], hcur_sa + rowA0 + wA1);
            ldsm_x4(ao1[0], ao1[1], ao1[2], ao1[3], hcur_sa + rowA1 + wA1);
#pragma unroll
            for (int g = 0; g < 3; g++)
#pragma unroll
                for (int nt = 0; nt < 2; nt++) {
                    unsigned b0, b1, b2, b3;
                    ldsm_x4(b0, b1, b2, b3, bAddr[g][nt] + wB);
                    mma_f16(acc[g][nt][0], ae0[0], ae0[1], ae0[2], ae0[3], b0, b1);
                    mma_f16(acc[g][nt][1], ae1[0], ae1[1], ae1[2], ae1[3], b0, b1);
                    mma_f16(acc[g][nt][0], ao0[0], ao0[1], ao0[2], ao0[3], b2, b3);
                    mma_f16(acc[g][nt][1], ao1[0], ao1[1], ao1[2], ao1[3], b2, b3);
                }
        }

        const bool wmix = (step >= 20);
#pragma unroll
        for (int e = 0; e < 4; e++) {
            const int mt = e >> 1, hh = e & 1;
            const int row = gid + 8 * e;
#pragma unroll
            for (int nt = 0; nt < 2; nt++) {
                const int wj = ct * 8 + nt * 4 + qid;
                __half2 xr = u2h2(gw[e][nt]);
                __half2 xz = u2h2(gw[e][2 + nt]);
                __half2 xn = u2h2(gw[e][4 + nt]);
                __half2 gr_ = __floats2half2_rn(acc[0][nt][mt][2 * hh], acc[0][nt][mt][2 * hh + 1]);
                __half2 gz_ = __floats2half2_rn(acc[1][nt][mt][2 * hh], acc[1][nt][mt][2 * hh + 1]);
                __half2 gn_ = __floats2half2_rn(acc[2][nt][mt][2 * hh], acc[2][nt][mt][2 * hh + 1]);
                __half2 r  = __hfma2(tanh2(__hmul2(__hadd2(xr, gr_), chalf)), chalf, chalf);
                __half2 z  = __hfma2(tanh2(__hmul2(__hadd2(xz, gz_), chalf)), chalf, chalf);
                __half2 cn = __hadd2(gn_, nt ? bn1 : bn0);
                __half2 n  = tanh2(__hfma2(r, cn, xn));
                __half2 h  = __hfma2(z, __hsub2(hreg[e][nt], n), n);
                hreg[e][nt] = h;
                unsigned hw = h22u(h);
                Hnxt[(row << 6) + (wj ^ (gid << 2))] = hw;
                if (wmix) g_mix[stream][row0 + row][t][wj] = hw;
            }
        }
        __syncthreads();
    }
}

// --------------------------------------------------------------- kernel 3 ---
// FUSED attn: computes C1 = mix_c @ W_cls^T IN SMEM (no g_C1 round-trip, no
// separate cls kernel), then Gram, col-softmax, logits MMA, row-softmax.
// Two batches per block; ~109.3 KB smem -> 2 blocks/SM.
#define UAW 68   // padded word stride (conflict-free fragments)
#define PTW 28   // Pm word stride (24 used + 4 pad; conflict-free)
#define UASZ (48 * UAW)
#define PMSZ (48 * PTW)
#define C1SZ (48 * CW_)
__global__ __launch_bounds__(256, 2) void attn_kernel(const float* __restrict__ W_cls,
                                                      const float* __restrict__ b_cls,
                                                      float* __restrict__ out) {
    extern __shared__ float sm[];
    unsigned* Uab = (unsigned*)sm;                  // [2][48][UAW]; later L f16x2 [40][52]
    unsigned* Wc  = Uab + 2 * UASZ;                 // [104][64] W_cls f16x2, swizzled
    unsigned* C1s = Wc + 104 * 64;                  // [2][48][CW_] (rows 40-47 zero)
    unsigned* Mst = C1s + 2 * C1SZ;                 // [48][64] mix_c staging, swizzled
    float*    E   = (float*)(Mst + 48 * 64);        // [2][1600]
    float*    Z   = E + 2 * 1600;                   // [2][40]
    unsigned* Pm  = (unsigned*)(Z + 80);            // [2][48][PTW]
    float*    bs  = (float*)(Pm + 2 * PMSZ);        // [104]

    const int b0 = blockIdx.x * 2, tid = threadIdx.x;
    const int warp = tid >> 5, lane = tid & 31;
    const int gid = lane >> 2, qid = lane & 3;
    const int l7 = lane & 7, grp = lane >> 3;
    const int gsw = gid << 2;

    // Phase 0: load mix_a (both batches), W_cls (f16-pack), bias, mix_c batch 0
#pragma unroll
    for (int bi = 0; bi < 2; bi++) {
        const unsigned* pma = &g_mix[0][b0 + bi][0][0];
        unsigned* Ub = Uab + bi * UASZ;
        for (int i = tid; i < UASZ; i += 256) {
            int t = i / UAW, w = i - t * UAW;
            Ub[i] = (t < 40 && w < 64) ? pma[t * 64 + w] : 0u;
        }
    }
    for (int i = tid; i < 104 * 64; i += 256) {
        int c = i >> 6, w = i & 63;
        float2 v;
        if (c < C_) v = *(const float2*)(W_cls + (size_t)c * 256 + 2 * w);
        else        v = make_float2(0.f, 0.f);
        Wc[(c << 6) + (w ^ ((c & 7) << 2))] = pack_f16(v.x, v.y);
    }
    for (int i = tid; i < CP_; i += 256) bs[i] = (i < C_) ? b_cls[i] : 0.f;
    {
        const unsigned* pmc = &g_mix[1][b0][0][0];
        for (int i = tid; i < 48 * 64; i += 256) {
            int t = i >> 6, w = i & 63;
            Mst[(t << 6) + (w ^ ((t & 7) << 2))] = (t < 40) ? pmc[t * 64 + w] : 0u;
        }
    }
    __syncthreads();

    // C1 build: 2 passes (shared staging). Pass bi: 39 tiles (3 m16 x 13 n8).
#pragma unroll
    for (int bi = 0; bi < 2; bi++) {
        if (bi == 1) {
            __syncthreads();   // pass-0 MMA reads done before staging overwrite
            const unsigned* pmc = &g_mix[1][b0 + 1][0][0];
            for (int i = tid; i < 48 * 64; i += 256) {
                int t = i >> 6, w = i & 63;
                Mst[(t << 6) + (w ^ ((t & 7) << 2))] = (t < 40) ? pmc[t * 64 + w] : 0u;
            }
            __syncthreads();
        }
#pragma unroll
        for (int j = 0; j < 5; j++) {
            const int idx = warp + 8 * j;
            if (idx < 39) {
                const int mt = idx / 13, nt = idx - mt * 13;
                const int ra0 = (mt * 16 + gid) << 6;
                const int ra1 = ra0 + (8 << 6);
                const unsigned* wr = Wc + ((nt * 8 + gid) << 6);
                float acc[4] = {0.f, 0.f, 0.f, 0.f};
#pragma unroll
                for (int kb = 0; kb < 8; kb++) {
                    const int k0 = kb * 8;
                    mma_f16(acc,
                            Mst[ra0 + ((k0 + qid)     ^ gsw)],
                            Mst[ra1 + ((k0 + qid)     ^ gsw)],
                            Mst[ra0 + ((k0 + qid + 4) ^ gsw)],
                            Mst[ra1 + ((k0 + qid + 4) ^ gsw)],
                            wr[(k0 + qid)     ^ gsw],
                            wr[(k0 + qid + 4) ^ gsw]);
                }
                unsigned* cp = C1s + bi * C1SZ;
                const int r0 = mt * 16 + gid;
                cp[r0 * CW_ + nt * 4 + qid]       = pack_f16(acc[0], acc[1]);
                cp[(r0 + 8) * CW_ + nt * 4 + qid] = pack_f16(acc[2], acc[3]);
            }
        }
    }
    // NOTE: no barrier needed before Gram (Gram reads Uab, writes E; disjoint)

    // Gram via f16 MMA: 15 tiles x 2 batches = 30 tasks over 8 warps.
#pragma unroll
    for (int j = 0; j < 4; j++) {
        const int idx = warp + 8 * j;
        if (idx < 30) {
            const int bi = idx / 15, t15 = idx - bi * 15;
            const int mi = t15 / 5, ni = t15 - mi * 5;
            const unsigned* Ub = Uab + bi * UASZ;
            const unsigned* A0 = Ub + (mi * 16 + gid) * UAW;
            const unsigned* A1 = A0 + 8 * UAW;
            const unsigned* B0 = Ub + (ni * 8 + gid) * UAW;
            float acc[4] = {0.f, 0.f, 0.f, 0.f};
#pragma unroll
            for (int kb = 0; kb < 8; kb++) {
                const int k0 = kb * 8;
                mma_f16(acc,
                        A0[k0 + qid], A1[k0 + qid], A0[k0 + qid + 4], A1[k0 + qid + 4],
                        B0[k0 + qid], B0[k0 + qid + 4]);
            }
            float* Eb = E + bi * 1600;
            const int r0 = mi * 16 + gid, c0 = ni * 8 + 2 * qid;
            Eb[r0 * 40 + c0]     = __expf(acc[0]);
            Eb[r0 * 40 + c0 + 1] = __expf(acc[1]);
            if (r0 + 8 < 40) {
                Eb[(r0 + 8) * 40 + c0]     = __expf(acc[2]);
                Eb[(r0 + 8) * 40 + c0 + 1] = __expf(acc[3]);
            }
        }
    }
    __syncthreads();

    if (tid < 80) {   // Z: 2 batches x 40 cols
        const int bi = tid / 40, t = tid - bi * 40;
        const float* Eb = E + bi * 1600;
        float z0 = 0.f, z1 = 0.f, z2 = 0.f, z3 = 0.f;
        for (int s = 0; s < 40; s += 4) {
            z0 += Eb[(s)     * 40 + t];
            z1 += Eb[(s + 1) * 40 + t];
            z2 += Eb[(s + 2) * 40 + t];
            z3 += Eb[(s + 3) * 40 + t];
        }
        Z[bi * 40 + t] = 1.f / ((z0 + z1) + (z2 + z3));
    }
    __syncthreads();

    // Build Pm for both batches
    for (int i = tid; i < 2 * PMSZ; i += 256) {
        const int bi = i / PMSZ, r = i - bi * PMSZ;
        const int s = r / PTW, w = r - s * PTW;
        unsigned v = 0u;
        if (s < 40 && w < 20) {
            const float* Eb = E + bi * 1600;
            const float* Zb = Z + bi * 40;
            v = pack_f16(Eb[s * 40 + 2 * w] * Zb[2 * w], Eb[s * 40 + 2 * w + 1] * Zb[2 * w + 1]);
        }
        Pm[i] = v;
    }
    __syncthreads();

    // Logits via f16 MMA: 39 tiles x 2 batches = 78 tasks over 8 warps.
    {
        const unsigned pm_sa = (unsigned)__cvta_generic_to_shared(Pm);
        const unsigned c1_sa = (unsigned)__cvta_generic_to_shared(C1s);
        const unsigned aLane = (unsigned)(((l7 + ((grp & 1) << 3)) * PTW + ((grp >> 1) << 2)) << 2);
        const unsigned bLane = (unsigned)(((lane & 15) * CW_) << 2);
#pragma unroll
        for (int j = 0; j < 10; j++) {
            const int idx = warp + 8 * j;
            if (idx < 78) {
                const int bi = idx / 39, t39 = idx - bi * 39;
                const int mt = t39 / 13, nt = t39 - mt * 13;
                const unsigned aBase = pm_sa + (unsigned)(bi * PMSZ * 4) + aLane
                                     + (unsigned)((mt * 16 * PTW) << 2);
                const unsigned bBase = c1_sa + (unsigned)(bi * C1SZ * 4) + bLane
                                     + (unsigned)((nt * 4) << 2);
                float acc[4] = {0.f, 0.f, 0.f, 0.f};
#pragma unroll
                for (int kt = 0; kt < 3; kt++) {
                    unsigned a0, a1, a2, a3, b0, b1;
                    ldsm_x4(a0, a1, a2, a3, aBase + kt * 32);
                    ldsm_x2t(b0, b1, bBase + kt * 16 * CW_ * 4);
                    mma_f16(acc, a0, a1, a2, a3, b0, b1);
                }
                unsigned* Lw = Uab + bi * UASZ;   // L overwrites Uab (dead after Gram)
                const int r0 = mt * 16 + gid, c0 = nt * 8 + 2 * qid;
                Lw[r0 * CW_ + nt * 4 + qid] = pack_f16(acc[0] + bs[c0], acc[1] + bs[c0 + 1]);
                if (r0 + 8 < 40)
                    Lw[(r0 + 8) * CW_ + nt * 4 + qid] = pack_f16(acc[2] + bs[c0], acc[3] + bs[c0 + 1]);
            }
        }
    }
    __syncthreads();

    // per-row softmax over classes: 80 rows over 8 warps
    for (int s8 = warp; s8 < 80; s8 += 8) {
        const int bi = s8 / 40, s = s8 - bi * 40;
        const unsigned* Lr = Uab + bi * UASZ + s * CW_;
        float m = -1e30f;
        for (int w = lane; w < 51; w += 32) {
            float2 v = h2f(Lr[w]);
            m = fmaxf(m, fmaxf(v.x, v.y));
        }
#pragma unroll
        for (int o = 16; o; o >>= 1) m = fmaxf(m, __shfl_xor_sync(~0u, m, o));
        float e[4]; int cnt = 0; float sum = 0.f;
        for (int w = lane; w < 51; w += 32) {
            float2 v = h2f(Lr[w]);
            float e0 = __expf(v.x - m), e1 = __expf(v.y - m);
            e[cnt++] = e0; e[cnt++] = e1; sum += e0 + e1;
        }
#pragma unroll
        for (int o = 16; o; o >>= 1) sum += __shfl_xor_sync(~0u, sum, o);
        float r = 1.f / sum; cnt = 0;
        float* op = out + ((size_t)(b0 + bi) * T_ + s) * C_;
        for (int w = lane; w < 51; w += 32) {
            op[2 * w]     = e[cnt++] * r;
            op[2 * w + 1] = e[cnt++] * r;
        }
    }
}

// ------------------------------------------------------------------ launch --
#define GX_SMEM   ((192 * 64 + 64 * 64 + 192) * 4)
#define SCAN_SMEM ((384 * 64 + 2 * 32 * 64 + 64) * 4)
#define ATTN_SMEM ((2 * UASZ + 104 * 64 + 2 * C1SZ + 48 * 64 + 2 * 1600 + 80 + 2 * PMSZ + CP_) * 4)

extern "C" void kernel_launch(void* const* d_in, const int* in_sizes, int n_in,
                              void* d_out, int out_size) {
    const int*   tokens = (const int*)  d_in[0];
    const float* emb_c  = (const float*)d_in[1];
    const float* emb_a  = (const float*)d_in[2];
    const float* W_ih   = (const float*)d_in[3];
    const float* W_hh   = (const float*)d_in[4];
    const float* b_ih   = (const float*)d_in[5];
    const float* b_hh   = (const float*)d_in[6];
    const float* W_cls  = (const float*)d_in[7];
    const float* b_cls  = (const float*)d_in[8];
    float* out = (float*)d_out;

    cudaFuncSetAttribute(tok_gx_kernel, cudaFuncAttributeMaxDynamicSharedMemorySize, GX_SMEM);
    cudaFuncSetAttribute(scan_kernel,   cudaFuncAttributeMaxDynamicSharedMemorySize, SCAN_SMEM);
    cudaFuncSetAttribute(attn_kernel,   cudaFuncAttributeMaxDynamicSharedMemorySize, ATTN_SMEM);

    tok_gx_kernel<<<dim3(70, 2, 2), 256, GX_SMEM>>>(emb_a, emb_c, W_ih, b_ih, b_hh);
    scan_kernel  <<<256,            256, SCAN_SMEM>>>(W_hh, b_hh, tokens);
    attn_kernel  <<<B_ / 2,         256, ATTN_SMEM>>>(W_cls, b_cls, out);
}